// round 8
// baseline (speedup 1.0000x reference)
#include <cuda_runtime.h>
#include <cstdint>

// Problem constants (K_Rectify): B=128, NTOT=129, N=128, GS=16, C=384
#define PB    128
#define PNTOT 129
#define PN    128
#define PGS   16
#define PC    384
#define EPSW  0.05f
#define RMSE  1e-6f

// C = 384 floats = 96 float4 per row. One CTA (96 threads) per output point.
// Blocks [0, B*N)      : compute one rectified point each.
// Blocks [B*N, B*N+B)  : copy the cls-token row for one batch each.
__global__ void __launch_bounds__(96, 16)
k_rectify_kernel(const float* __restrict__ f,
                 const float* __restrict__ dist,
                 const float* __restrict__ rf,
                 const float* __restrict__ knw,
                 const int* __restrict__ idx,        // int32! (JAX x64 disabled)
                 float* __restrict__ out)
{
    const int p   = blockIdx.x;
    const int tid = threadIdx.x;

    if (p >= PB * PN) {
        // cls-token copy: out[b, 0, :] = f[b, 0, :]
        const int b = p - PB * PN;
        const float4* src = reinterpret_cast<const float4*>(f  + (size_t)b * PNTOT * PC);
        float4*       dst = reinterpret_cast<float4*>(out + (size_t)b * PNTOT * PC);
        dst[tid] = src[tid];
        return;
    }

    const int b = p >> 7;        // p / PN
    const int n = p & (PN - 1);  // p % PN

    __shared__ float sw[PGS];        // normalized weights
    __shared__ int   soff[PGS];      // gather row offsets (in floats, < 2^23 so int is safe)
    __shared__ float sred[3];        // per-warp partial sums for RMS

    if (tid < PGS) {
        float d  = dist[p * PGS + tid];
        float wv = 1.0f / (d + EPSW);
        float s  = wv;
        #pragma unroll
        for (int o = 8; o > 0; o >>= 1)
            s += __shfl_xor_sync(0x0000FFFFu, s, o, 16);
        sw[tid] = wv / s;

        const int j  = idx[p * PGS + tid];   // j in [0, B*N)
        const int bb = j >> 7;               // j / PN
        const int nn = j & (PN - 1);         // j % PN
        soff[tid] = (bb * PNTOT + 1 + nn) * PC;
    }
    __syncthreads();

    // x row (this point) and weighted neighbor accumulation
    const float4* xr = reinterpret_cast<const float4*>(f + (size_t)(b * PNTOT + 1 + n) * PC);
    float4 x4 = xr[tid];

    float a0 = 0.f, a1 = 0.f, a2 = 0.f, a3 = 0.f;
    #pragma unroll
    for (int g = 0; g < PGS; g++) {
        const float4 nb = reinterpret_cast<const float4*>(f + (size_t)soff[g])[tid];
        const float wv = sw[g];
        a0 = fmaf(wv, nb.x, a0);
        a1 = fmaf(wv, nb.y, a1);
        a2 = fmaf(wv, nb.z, a2);
        a3 = fmaf(wv, nb.w, a3);
    }
    // sf = (sum_g w_g * neighbor_g) - x   (weights sum to 1)
    float s0 = a0 - x4.x;
    float s1 = a1 - x4.y;
    float s2 = a2 - x4.z;
    float s3 = a3 - x4.w;

    // RMS over the 384-channel row
    float ss = s0 * s0 + s1 * s1 + s2 * s2 + s3 * s3;
    #pragma unroll
    for (int o = 16; o > 0; o >>= 1)
        ss += __shfl_xor_sync(0xFFFFFFFFu, ss, o);
    if ((tid & 31) == 0) sred[tid >> 5] = ss;
    __syncthreads();
    const float tot = sred[0] + sred[1] + sred[2];
    const float inv = rsqrtf(tot * (1.0f / PC) + RMSE);

    // out = rf[1+n] + x + (sf * inv) * knorm_w
    const float4 r4 = reinterpret_cast<const float4*>(rf + (size_t)(1 + n) * PC)[tid];
    const float4 k4 = reinterpret_cast<const float4*>(knw)[tid];

    float4 o4;
    o4.x = r4.x + x4.x + s0 * inv * k4.x;
    o4.y = r4.y + x4.y + s1 * inv * k4.y;
    o4.z = r4.z + x4.z + s2 * inv * k4.z;
    o4.w = r4.w + x4.w + s3 * inv * k4.w;

    reinterpret_cast<float4*>(out + (size_t)(b * PNTOT + 1 + n) * PC)[tid] = o4;
}

extern "C" void kernel_launch(void* const* d_in, const int* in_sizes, int n_in,
                              void* d_out, int out_size)
{
    const float* f    = (const float*)d_in[0];
    const float* dist = (const float*)d_in[1];
    const float* rf   = (const float*)d_in[2];
    const float* knw  = (const float*)d_in[3];
    const int*   idx  = (const int*)d_in[4];
    float*       out  = (float*)d_out;

    const int grid = PB * PN + PB;   // 16384 compute blocks + 128 cls-copy blocks
    k_rectify_kernel<<<grid, 96>>>(f, dist, rf, knw, idx, out);
}